// round 1
// baseline (speedup 1.0000x reference)
#include <cuda_runtime.h>

#define NR 8192
#define NT 8192
#define RB 64
#define CB 64

// Scratch (device globals — no allocation allowed)
__device__ float g_A[NR * CB];        // per-row col-block sums, 2 MB
__device__ int   g_row_cum[RB + 1];
__device__ int   g_col_cum[CB + 1];

// ---------------------------------------------------------------------------
// Kernel 1: block counts + cumulative boundaries (exact, int atomics)
// ---------------------------------------------------------------------------
__global__ void k_setup(const int* __restrict__ row_ids,
                        const int* __restrict__ col_ids) {
    __shared__ int rc[RB];
    __shared__ int cc[CB];
    int t = threadIdx.x;
    if (t < RB) rc[t] = 0;
    if (t < CB) cc[t] = 0;
    __syncthreads();
    for (int i = t; i < NR; i += blockDim.x) atomicAdd(&rc[row_ids[i]], 1);
    for (int i = t; i < NT; i += blockDim.x) atomicAdd(&cc[col_ids[i]], 1);
    __syncthreads();
    if (t == 0) {
        int s = 0;
        g_row_cum[0] = 0;
        for (int b = 0; b < RB; b++) { s += rc[b]; g_row_cum[b + 1] = s; }
        s = 0;
        g_col_cum[0] = 0;
        for (int b = 0; b < CB; b++) { s += cc[b]; g_col_cum[b + 1] = s; }
    }
}

// ---------------------------------------------------------------------------
// Kernel 2: per-row column-block sums (the 256 MB bandwidth pass)
// One CTA per row, 256 threads. Coalesced float4 loads -> padded shared
// staging -> each thread reduces a contiguous 32-col chunk with a
// segment-boundary walk; rare flushes via shared atomicAdd.
// ---------------------------------------------------------------------------
__global__ __launch_bounds__(256) void k_colsum(const float* __restrict__ X) {
    __shared__ float srow[NT + NT / 32];   // padded: word(c) = c + (c>>5)
    __shared__ float ssum[CB];
    __shared__ int   scum[CB + 1];

    const int t   = threadIdx.x;
    const int row = blockIdx.x;

    if (t < CB)  ssum[t] = 0.0f;
    if (t <= CB) scum[t] = g_col_cum[t];

    // Coalesced load of the full row (8 float4 per thread)
    const float4* Xr = (const float4*)(X + (size_t)row * NT);
    float4 v[8];
#pragma unroll
    for (int s = 0; s < 8; s++) v[s] = Xr[t + 256 * s];

    // Store to padded shared (conflict-free scalar STS; 4f..4f+3 never
    // crosses a 32-boundary so padding offset is uniform within a float4)
#pragma unroll
    for (int s = 0; s < 8; s++) {
        int f = t + 256 * s;
        int w = 4 * f + (f >> 3);
        srow[w + 0] = v[s].x;
        srow[w + 1] = v[s].y;
        srow[w + 2] = v[s].z;
        srow[w + 3] = v[s].w;
    }
    __syncthreads();

    // Reduce contiguous columns [32t, 32t+32)
    const int c0 = t * 32;
    // binary search: largest cb with scum[cb] <= c0
    int lo = 0, hi = CB;
    while (lo < hi) {
        int mid = (lo + hi + 1) >> 1;
        if (scum[mid] <= c0) lo = mid; else hi = mid - 1;
    }
    int cb = lo;
    int nb = scum[cb + 1];

    float acc = 0.0f;
    const int base = 33 * t;   // word(32t) = 32t + t
#pragma unroll
    for (int j = 0; j < 32; j++) {
        int c = c0 + j;
        while (c >= nb) {
            if (acc != 0.0f) atomicAdd(&ssum[cb], acc);
            acc = 0.0f;
            cb++;
            nb = scum[cb + 1];
        }
        acc += srow[base + j];
    }
    if (acc != 0.0f) atomicAdd(&ssum[cb], acc);

    __syncthreads();
    if (t < CB) g_A[row * CB + t] = ssum[t];
}

// ---------------------------------------------------------------------------
// Kernel 3: segment-sum over rows (fixed order, deterministic), block mean,
// 1->3->3->1 ReLU MLP, sigmoid, plus cumsum outputs.
// Grid: RB CTAs x CB threads.
// ---------------------------------------------------------------------------
__global__ void k_final(const float* __restrict__ W1, const float* __restrict__ b1,
                        const float* __restrict__ W2, const float* __restrict__ b2,
                        const float* __restrict__ W3, const float* __restrict__ b3,
                        float* __restrict__ out, int out_size) {
    const int rb = blockIdx.x;
    const int cb = threadIdx.x;

    const int r0 = g_row_cum[rb];
    const int r1 = g_row_cum[rb + 1];

    float s = 0.0f;
    for (int r = r0; r < r1; r++) s += g_A[r * CB + cb];   // coalesced over cb

    const float rcount = (float)(r1 - r0);
    const float ccount = (float)(g_col_cum[cb + 1] - g_col_cum[cb]);
    const float x = s / (rcount * ccount);

    float h1[3], h2[3];
#pragma unroll
    for (int k = 0; k < 3; k++) h1[k] = fmaxf(x * W1[k] + b1[k], 0.0f);
#pragma unroll
    for (int j = 0; j < 3; j++) {
        float z = b2[j];
#pragma unroll
        for (int k = 0; k < 3; k++) z += h1[k] * W2[k * 3 + j];
        h2[j] = fmaxf(z, 0.0f);
    }
    float z = b3[0];
#pragma unroll
    for (int j = 0; j < 3; j++) z += h2[j] * W3[j];

    out[rb * CB + cb] = 1.0f / (1.0f + expf(-z));

    // Tail outputs: row_cumsum[65], col_cumsum[65] as float
    if (rb == 0 && out_size >= RB * CB + 2 * (RB + 1)) {
        for (int i = cb; i <= RB; i += CB)
            out[RB * CB + i] = (float)g_row_cum[i];
        for (int i = cb; i <= CB; i += CB)
            out[RB * CB + (RB + 1) + i] = (float)g_col_cum[i];
    }
}

// ---------------------------------------------------------------------------
extern "C" void kernel_launch(void* const* d_in, const int* in_sizes, int n_in,
                              void* d_out, int out_size) {
    const float* X       = (const float*)d_in[0];
    const int*   row_ids = (const int*)d_in[1];
    const int*   col_ids = (const int*)d_in[2];
    const float* W1      = (const float*)d_in[3];
    const float* b1      = (const float*)d_in[4];
    const float* W2      = (const float*)d_in[5];
    const float* b2      = (const float*)d_in[6];
    const float* W3      = (const float*)d_in[7];
    const float* b3      = (const float*)d_in[8];
    float* out = (float*)d_out;

    k_setup<<<1, 256>>>(row_ids, col_ids);
    k_colsum<<<NR, 256>>>(X);
    k_final<<<RB, CB>>>(W1, b1, W2, b2, W3, b3, out, out_size);
}

// round 2
// speedup vs baseline: 1.1656x; 1.1656x over previous
#include <cuda_runtime.h>

#define NR 8192
#define NT 8192
#define RB 64
#define CB 64

// Scratch (device globals — no allocation allowed)
__device__ float g_A[NR * CB];        // per-row col-block sums, 2 MB
__device__ int   g_row_cum[RB + 1];
__device__ int   g_col_cum[CB + 1];

// ---------------------------------------------------------------------------
// Kernel 1: cumulative block boundaries via sorted-id transition detection.
// cum[b] = first index i with id[i] >= b. Exact, atomic-free, fully parallel.
// ---------------------------------------------------------------------------
__global__ void k_setup(const int* __restrict__ row_ids,
                        const int* __restrict__ col_ids) {
    int i = blockIdx.x * blockDim.x + threadIdx.x;
    if (i < NR) {
        int cur  = row_ids[i];
        int prev = i ? row_ids[i - 1] : -1;
        for (int b = prev + 1; b <= cur; b++) g_row_cum[b] = i;
        if (i == NR - 1)
            for (int b = cur + 1; b <= RB; b++) g_row_cum[b] = NR;
    }
    if (i < NT) {
        int cur  = col_ids[i];
        int prev = i ? col_ids[i - 1] : -1;
        for (int b = prev + 1; b <= cur; b++) g_col_cum[b] = i;
        if (i == NT - 1)
            for (int b = cur + 1; b <= CB; b++) g_col_cum[b] = NT;
    }
}

// ---------------------------------------------------------------------------
// Kernel 2: per-row column-block sums (the 256 MB bandwidth pass).
// One CTA (256 thr, 8 warps) per row; each warp autonomously handles 1024
// contiguous columns: coalesced float4 loads -> XOR-swizzled smem (bank
// conflict-free for both STS.128 and LDS.128) -> __syncwarp -> per-lane
// 32-column segment walk. No CTA-wide barrier between load and reduce,
// so warps stagger and DRAM stays busy.
// ---------------------------------------------------------------------------
__global__ __launch_bounds__(256) void k_colsum(const float* __restrict__ X) {
    __shared__ float4 sbuf[8][256];     // 32 KB, per-warp 256 float4
    __shared__ float  wsum[8][CB];      // per-warp partial block sums
    __shared__ int    scum[CB + 1];

    const int t   = threadIdx.x & 31;   // lane
    const int w   = threadIdx.x >> 5;   // warp
    const int row = blockIdx.x;

    // Per-warp init (redundant same-value writes to scum are benign)
    for (int i = t; i < CB; i += 32) wsum[w][i] = 0.0f;
    for (int i = t; i <= CB; i += 32) scum[i] = g_col_cum[i];

    // Coalesced load of this warp's 4 KB slice (8 float4 per lane)
    const float4* Xr = (const float4*)(X + (size_t)row * NT) + (w << 8);
    float4 v[8];
#pragma unroll
    for (int s = 0; s < 8; s++) v[s] = Xr[t + 32 * s];

    // Swizzled store: phys = f ^ ((f>>3)&7) — conflict-free STS.128
#pragma unroll
    for (int s = 0; s < 8; s++) {
        int f = t + 32 * s;
        sbuf[w][f ^ ((f >> 3) & 7)] = v[s];
    }
    __syncwarp();

    // Gather this lane's contiguous 32-column chunk (conflict-free LDS.128)
    float r[32];
#pragma unroll
    for (int j = 0; j < 8; j++) {
        int f = 8 * t + j;
        float4 q = sbuf[w][f ^ ((f >> 3) & 7)];
        r[4 * j + 0] = q.x; r[4 * j + 1] = q.y;
        r[4 * j + 2] = q.z; r[4 * j + 3] = q.w;
    }

    // Segment walk over cols [c0, c0+32)
    const int c0 = (w << 10) + (t << 5);
    int lo = 0, hi = CB;
    while (lo < hi) {                   // largest cb with scum[cb] <= c0
        int mid = (lo + hi + 1) >> 1;
        if (scum[mid] <= c0) lo = mid; else hi = mid - 1;
    }
    int cb = lo;
    int nb = scum[cb + 1];
    float acc = 0.0f;
#pragma unroll
    for (int j = 0; j < 32; j++) {
        int c = c0 + j;
        while (c >= nb) {
            if (acc != 0.0f) atomicAdd(&wsum[w][cb], acc);
            acc = 0.0f;
            cb++;
            nb = scum[cb + 1];
        }
        acc += r[j];
    }
    if (acc != 0.0f) atomicAdd(&wsum[w][cb], acc);

    __syncthreads();
    if (threadIdx.x < CB) {
        float s = 0.0f;
#pragma unroll
        for (int q = 0; q < 8; q++) s += wsum[q][threadIdx.x];
        g_A[row * CB + threadIdx.x] = s;
    }
}

// ---------------------------------------------------------------------------
// Kernel 3: segment-sum over rows (fixed deterministic 4-way split), block
// mean, 1->3->3->1 ReLU MLP, sigmoid, plus cumsum tail outputs.
// Grid: RB CTAs x 256 threads.
// ---------------------------------------------------------------------------
__global__ void k_final(const float* __restrict__ W1, const float* __restrict__ b1,
                        const float* __restrict__ W2, const float* __restrict__ b2,
                        const float* __restrict__ W3, const float* __restrict__ b3,
                        float* __restrict__ out, int out_size) {
    __shared__ float part[4][CB];
    const int rb = blockIdx.x;
    const int cb = threadIdx.x & 63;
    const int q  = threadIdx.x >> 6;

    const int r0 = g_row_cum[rb];
    const int r1 = g_row_cum[rb + 1];
    const int n  = r1 - r0;
    const int qs = r0 + (n * q) / 4;
    const int qe = r0 + (n * (q + 1)) / 4;

    float s = 0.0f;
    for (int r = qs; r < qe; r++) s += g_A[r * CB + cb];   // coalesced over cb
    part[q][cb] = s;
    __syncthreads();

    if (threadIdx.x < CB) {
        s = part[0][cb] + part[1][cb] + part[2][cb] + part[3][cb];

        const float rcount = (float)n;
        const float ccount = (float)(g_col_cum[cb + 1] - g_col_cum[cb]);
        const float x = s / (rcount * ccount);

        float h1[3], h2[3];
#pragma unroll
        for (int k = 0; k < 3; k++) h1[k] = fmaxf(x * W1[k] + b1[k], 0.0f);
#pragma unroll
        for (int j = 0; j < 3; j++) {
            float z = b2[j];
#pragma unroll
            for (int k = 0; k < 3; k++) z += h1[k] * W2[k * 3 + j];
            h2[j] = fmaxf(z, 0.0f);
        }
        float z = b3[0];
#pragma unroll
        for (int j = 0; j < 3; j++) z += h2[j] * W3[j];

        out[rb * CB + cb] = 1.0f / (1.0f + expf(-z));
    }

    // Tail outputs: row_cumsum[65], col_cumsum[65] as float
    if (rb == 0 && out_size >= RB * CB + 2 * (RB + 1) && threadIdx.x < CB) {
        for (int i = cb; i <= RB; i += CB)
            out[RB * CB + i] = (float)g_row_cum[i];
        for (int i = cb; i <= CB; i += CB)
            out[RB * CB + (RB + 1) + i] = (float)g_col_cum[i];
    }
}

// ---------------------------------------------------------------------------
extern "C" void kernel_launch(void* const* d_in, const int* in_sizes, int n_in,
                              void* d_out, int out_size) {
    const float* X       = (const float*)d_in[0];
    const int*   row_ids = (const int*)d_in[1];
    const int*   col_ids = (const int*)d_in[2];
    const float* W1      = (const float*)d_in[3];
    const float* b1      = (const float*)d_in[4];
    const float* W2      = (const float*)d_in[5];
    const float* b2      = (const float*)d_in[6];
    const float* W3      = (const float*)d_in[7];
    const float* b3      = (const float*)d_in[8];
    float* out = (float*)d_out;

    k_setup<<<32, 256>>>(row_ids, col_ids);
    k_colsum<<<NR, 256>>>(X);
    k_final<<<RB, 256>>>(W1, b1, W2, b2, W3, b3, out, out_size);
}